// round 3
// baseline (speedup 1.0000x reference)
#include <cuda_runtime.h>

#define N_NODES 50000
#define N_EDGES 800000
#define IN_CH 64
#define OUT_CH 64
#define N_REL 8
#define N_BASES 4
#define NJ 576          // 512 xw cols (8 rel * 64) + 64 root cols
#define XW_COLS 512

// Scratch (allocation-free: __device__ globals). float4-typed => 16B aligned,
// safe for LDG.128 / STG.128 / red.global.add.v4.f32.
__device__ float4 g_W4[IN_CH * NJ / 4];                  // combined weights [i][j]
__device__ float4 g_xw4[(size_t)N_NODES * XW_COLS / 4];  // node-major [N, 512]
__device__ float4 g_agg04[(size_t)N_NODES * OUT_CH / 4]; // layer-0 accumulator

// ---------------------------------------------------------------------------
// Kernel 1: combine basis weights + pack root into one [64 x 576] matrix
// ---------------------------------------------------------------------------
__global__ void combine_w_kernel(const float* __restrict__ basis,   // [B, in, out]
                                 const float* __restrict__ att,     // [R, B]
                                 const float* __restrict__ root) {  // [in, out]
    int idx = blockIdx.x * blockDim.x + threadIdx.x;
    if (idx >= IN_CH * NJ) return;
    int i = idx / NJ;
    int j = idx - i * NJ;
    float v;
    if (j < XW_COLS) {
        int r = j >> 6;
        int c = j & 63;
        v = 0.f;
#pragma unroll
        for (int b = 0; b < N_BASES; b++)
            v += att[r * N_BASES + b] * basis[(b * IN_CH + i) * OUT_CH + c];
    } else {
        v = root[i * OUT_CH + (j - XW_COLS)];
    }
    reinterpret_cast<float*>(g_W4)[i * NJ + j] = v;
}

// ---------------------------------------------------------------------------
// Kernel 2: node GEMM. out[n, 0:512] -> g_xw, out[n, 512:576]+bias -> agg
// BM=128 nodes, BK=64 (full), col tiles of 64 (9 tiles). 256 thr, 8x4 micro.
// ---------------------------------------------------------------------------
template <bool RELU>
__global__ void __launch_bounds__(256)
node_gemm_kernel(const float* __restrict__ h,
                 const float* __restrict__ bias,
                 float* __restrict__ agg) {
    __shared__ float sA[128][64];   // 32 KB
    __shared__ float sB[64][64];    // 16 KB

    const int tid = threadIdx.x;
    const int tx = tid & 15;        // col group (4 cols each)
    const int ty = tid >> 4;        // row group (8 rows each)
    const int nodeBase = blockIdx.x * 128;
    const float* W = reinterpret_cast<const float*>(g_W4);
    float* xw = reinterpret_cast<float*>(g_xw4);

    // Load A tile: 128 x 64 floats = 2048 float4, 8 per thread
#pragma unroll
    for (int k = tid; k < 128 * 16; k += 256) {
        int row = k >> 4;
        int c4 = k & 15;
        int n = nodeBase + row;
        float4 v = make_float4(0.f, 0.f, 0.f, 0.f);
        if (n < N_NODES)
            v = *reinterpret_cast<const float4*>(h + (size_t)n * IN_CH + c4 * 4);
        if (RELU) {
            v.x = fmaxf(v.x, 0.f); v.y = fmaxf(v.y, 0.f);
            v.z = fmaxf(v.z, 0.f); v.w = fmaxf(v.w, 0.f);
        }
        *reinterpret_cast<float4*>(&sA[row][c4 * 4]) = v;
    }
    __syncthreads();

#pragma unroll 1
    for (int jt = 0; jt < 9; jt++) {
        // Load B tile: W[i][jt*64 + c], 64x64 floats = 1024 float4, 4/thread
#pragma unroll
        for (int k = tid; k < 64 * 16; k += 256) {
            int i = k >> 4;
            int c4 = k & 15;
            *reinterpret_cast<float4*>(&sB[i][c4 * 4]) =
                *reinterpret_cast<const float4*>(W + i * NJ + jt * 64 + c4 * 4);
        }
        __syncthreads();

        float acc[8][4];
#pragma unroll
        for (int m = 0; m < 8; m++)
#pragma unroll
            for (int q = 0; q < 4; q++) acc[m][q] = 0.f;

#pragma unroll
        for (int i = 0; i < 64; i++) {
            float4 b4 = *reinterpret_cast<const float4*>(&sB[i][tx * 4]);
#pragma unroll
            for (int m = 0; m < 8; m++) {
                float a = sA[ty * 8 + m][i];
                acc[m][0] = fmaf(a, b4.x, acc[m][0]);
                acc[m][1] = fmaf(a, b4.y, acc[m][1]);
                acc[m][2] = fmaf(a, b4.z, acc[m][2]);
                acc[m][3] = fmaf(a, b4.w, acc[m][3]);
            }
        }

        // Store
        if (jt < 8) {
            int jBase = jt * 64 + tx * 4;
#pragma unroll
            for (int m = 0; m < 8; m++) {
                int n = nodeBase + ty * 8 + m;
                if (n < N_NODES) {
                    *reinterpret_cast<float4*>(&xw[(size_t)n * XW_COLS + jBase]) =
                        make_float4(acc[m][0], acc[m][1], acc[m][2], acc[m][3]);
                }
            }
        } else {
            int c = tx * 4;
            float4 bv = *reinterpret_cast<const float4*>(bias + c);
#pragma unroll
            for (int m = 0; m < 8; m++) {
                int n = nodeBase + ty * 8 + m;
                if (n < N_NODES) {
                    *reinterpret_cast<float4*>(agg + (size_t)n * OUT_CH + c) =
                        make_float4(acc[m][0] + bv.x, acc[m][1] + bv.y,
                                    acc[m][2] + bv.z, acc[m][3] + bv.w);
                }
            }
        }
        __syncthreads();
    }
}

// ---------------------------------------------------------------------------
// Kernel 3: edge gather + scatter. Half-warp (16 lanes) per edge, 4 ch/lane.
// msg[e,c] = sum_r ea[e,r] * xw[src[e], r*64 + c]; red into agg[dst[e], c].
// edge_index is INT32 (JAX x64 disabled downcasts the declared int64).
// ---------------------------------------------------------------------------
__global__ void __launch_bounds__(256)
edge_kernel(const int* __restrict__ ei,         // [2, E] int32
            const float* __restrict__ ea,       // [E, 8]
            float* __restrict__ agg) {
    int t = blockIdx.x * blockDim.x + threadIdx.x;
    int e = t >> 4;
    int l = t & 15;
    if (e >= N_EDGES) return;

    int src = ei[e];
    int dst = ei[N_EDGES + e];
    // Defensive: if dtype inference is wrong we get wrong results (diagnosable
    // via rel_err) rather than an opaque IMA.
    if ((unsigned)src >= N_NODES || (unsigned)dst >= N_NODES) return;

    const float* eb = ea + (size_t)e * N_REL;
    const float4* xs = g_xw4 + (size_t)src * (XW_COLS / 4);

    float4 acc = make_float4(0.f, 0.f, 0.f, 0.f);
#pragma unroll
    for (int r = 0; r < N_REL; r++) {
        float w = __ldg(eb + r);
        float4 v = xs[r * 16 + l];
        acc.x = fmaf(w, v.x, acc.x);
        acc.y = fmaf(w, v.y, acc.y);
        acc.z = fmaf(w, v.z, acc.z);
        acc.w = fmaf(w, v.w, acc.w);
    }

    float* out = agg + (size_t)dst * OUT_CH + l * 4;
    asm volatile("red.global.add.v4.f32 [%0], {%1, %2, %3, %4};"
                 :: "l"(out), "f"(acc.x), "f"(acc.y), "f"(acc.z), "f"(acc.w)
                 : "memory");
}

// ---------------------------------------------------------------------------
// Launch
// ---------------------------------------------------------------------------
extern "C" void kernel_launch(void* const* d_in, const int* in_sizes, int n_in,
                              void* d_out, int out_size) {
    const float* x        = (const float*)d_in[0];
    const int* ei         = (const int*)d_in[1];     // int32 (see edge_kernel)
    const float* ea       = (const float*)d_in[2];
    const float* basis    = (const float*)d_in[3];   // [2, 4, 64, 64]
    const float* att      = (const float*)d_in[4];   // [2, 8, 4]
    const float* root     = (const float*)d_in[5];   // [2, 64, 64]
    const float* bias     = (const float*)d_in[6];   // [2, 64]
    float* out            = (float*)d_out;

    void* agg0_p = nullptr;
    cudaGetSymbolAddress(&agg0_p, g_agg04);
    float* agg0 = (float*)agg0_p;

    const int combineBlocks = (IN_CH * NJ + 255) / 256;
    const int gemmBlocks = (N_NODES + 127) / 128;
    const int edgeBlocks = (N_EDGES * 16 + 255) / 256;

    // ---- Layer 0 ----
    combine_w_kernel<<<combineBlocks, 256>>>(basis, att, root);
    node_gemm_kernel<false><<<gemmBlocks, 256>>>(x, bias, agg0);
    edge_kernel<<<edgeBlocks, 256>>>(ei, ea, agg0);

    // ---- Layer 1 (input = relu(agg0), output = d_out) ----
    const float* basis1 = basis + N_BASES * IN_CH * OUT_CH;
    const float* att1   = att + N_REL * N_BASES;
    const float* root1  = root + IN_CH * OUT_CH;
    const float* bias1  = bias + OUT_CH;

    combine_w_kernel<<<combineBlocks, 256>>>(basis1, att1, root1);
    node_gemm_kernel<true><<<gemmBlocks, 256>>>(agg0, bias1, out);
    edge_kernel<<<edgeBlocks, 256>>>(ei, ea, out);
}

// round 4
// speedup vs baseline: 1.6730x; 1.6730x over previous
#include <cuda_runtime.h>

#define N_NODES 50000
#define N_EDGES 800000
#define IN_CH 64
#define OUT_CH 64
#define N_REL 8
#define N_BASES 4
#define XB_COLS 256            // 4 bases * 64 out
#define NJ 320                 // 256 xb cols + 64 root cols

// Scratch (__device__ globals; float4-typed => 16B aligned)
__device__ float4 g_xb4[(size_t)N_NODES * XB_COLS / 4];  // node-major [N, 256]
__device__ float4 g_eb4[(size_t)N_EDGES];                // per-edge basis weights [E, 4]
__device__ float4 g_agg04[(size_t)N_NODES * OUT_CH / 4]; // layer-0 accumulator

// ---------------------------------------------------------------------------
// Kernel 1: project edge attrs to basis space: eb[e,b] = sum_r ea[e,r]*att[r,b]
// ---------------------------------------------------------------------------
__global__ void __launch_bounds__(256)
eb_kernel(const float* __restrict__ ea,    // [E, 8]
          const float* __restrict__ att) { // [R=8, B=4]
    __shared__ float sAtt[N_REL][N_BASES];
    if (threadIdx.x < N_REL * N_BASES)
        reinterpret_cast<float*>(sAtt)[threadIdx.x] = att[threadIdx.x];
    __syncthreads();

    int e = blockIdx.x * blockDim.x + threadIdx.x;
    if (e >= N_EDGES) return;

    const float4* ep = reinterpret_cast<const float4*>(ea + (size_t)e * N_REL);
    float4 a0 = ep[0];
    float4 a1 = ep[1];
    float r[8] = {a0.x, a0.y, a0.z, a0.w, a1.x, a1.y, a1.z, a1.w};

    float4 o = make_float4(0.f, 0.f, 0.f, 0.f);
#pragma unroll
    for (int k = 0; k < N_REL; k++) {
        o.x = fmaf(r[k], sAtt[k][0], o.x);
        o.y = fmaf(r[k], sAtt[k][1], o.y);
        o.z = fmaf(r[k], sAtt[k][2], o.z);
        o.w = fmaf(r[k], sAtt[k][3], o.w);
    }
    g_eb4[e] = o;
}

// ---------------------------------------------------------------------------
// Kernel 2: node GEMM. B matrix is [basis | root] read directly from inputs.
//   cols 0..255  -> g_xb4  (xb = h @ basis[b], laid out [n][b*64+c])
//   cols 256..319 -> agg = h @ root + bias
// BM=128 nodes, BK=64 (full), 5 col tiles of 64. 256 thr, 8x4 micro.
// ---------------------------------------------------------------------------
template <bool RELU>
__global__ void __launch_bounds__(256)
node_gemm_kernel(const float* __restrict__ h,
                 const float* __restrict__ basis,  // [B=4, 64, 64], tile b is contiguous
                 const float* __restrict__ root,   // [64, 64]
                 const float* __restrict__ bias,   // [64]
                 float* __restrict__ agg) {
    __shared__ float sA[128][64];   // 32 KB
    __shared__ float sB[64][64];    // 16 KB

    const int tid = threadIdx.x;
    const int tx = tid & 15;        // col group (4 cols each)
    const int ty = tid >> 4;        // row group (8 rows each)
    const int nodeBase = blockIdx.x * 128;
    float* xb = reinterpret_cast<float*>(g_xb4);

    // Load A tile: 128 x 64 floats = 2048 float4, 8 per thread
#pragma unroll
    for (int k = tid; k < 128 * 16; k += 256) {
        int row = k >> 4;
        int c4 = k & 15;
        int n = nodeBase + row;
        float4 v = make_float4(0.f, 0.f, 0.f, 0.f);
        if (n < N_NODES)
            v = *reinterpret_cast<const float4*>(h + (size_t)n * IN_CH + c4 * 4);
        if (RELU) {
            v.x = fmaxf(v.x, 0.f); v.y = fmaxf(v.y, 0.f);
            v.z = fmaxf(v.z, 0.f); v.w = fmaxf(v.w, 0.f);
        }
        *reinterpret_cast<float4*>(&sA[row][c4 * 4]) = v;
    }
    __syncthreads();

#pragma unroll 1
    for (int jt = 0; jt < 5; jt++) {
        // Load B tile: basis[jt] (a contiguous 64x64 block) or root
        const float* Bsrc = (jt < N_BASES) ? (basis + jt * IN_CH * OUT_CH) : root;
#pragma unroll
        for (int k = tid; k < 64 * 16; k += 256) {
            int i = k >> 4;
            int c4 = k & 15;
            *reinterpret_cast<float4*>(&sB[i][c4 * 4]) =
                *reinterpret_cast<const float4*>(Bsrc + i * OUT_CH + c4 * 4);
        }
        __syncthreads();

        float acc[8][4];
#pragma unroll
        for (int m = 0; m < 8; m++)
#pragma unroll
            for (int q = 0; q < 4; q++) acc[m][q] = 0.f;

#pragma unroll
        for (int i = 0; i < 64; i++) {
            float4 b4 = *reinterpret_cast<const float4*>(&sB[i][tx * 4]);
#pragma unroll
            for (int m = 0; m < 8; m++) {
                float a = sA[ty * 8 + m][i];
                acc[m][0] = fmaf(a, b4.x, acc[m][0]);
                acc[m][1] = fmaf(a, b4.y, acc[m][1]);
                acc[m][2] = fmaf(a, b4.z, acc[m][2]);
                acc[m][3] = fmaf(a, b4.w, acc[m][3]);
            }
        }

        if (jt < N_BASES) {
            int jBase = jt * 64 + tx * 4;
#pragma unroll
            for (int m = 0; m < 8; m++) {
                int n = nodeBase + ty * 8 + m;
                if (n < N_NODES) {
                    *reinterpret_cast<float4*>(&xb[(size_t)n * XB_COLS + jBase]) =
                        make_float4(acc[m][0], acc[m][1], acc[m][2], acc[m][3]);
                }
            }
        } else {
            int c = tx * 4;
            float4 bv = *reinterpret_cast<const float4*>(bias + c);
#pragma unroll
            for (int m = 0; m < 8; m++) {
                int n = nodeBase + ty * 8 + m;
                if (n < N_NODES) {
                    *reinterpret_cast<float4*>(agg + (size_t)n * OUT_CH + c) =
                        make_float4(acc[m][0] + bv.x, acc[m][1] + bv.y,
                                    acc[m][2] + bv.z, acc[m][3] + bv.w);
                }
            }
        }
        __syncthreads();
    }
}

// ---------------------------------------------------------------------------
// Kernel 3: edge gather + scatter in basis space. Half-warp per edge.
// msg[e,c] = sum_b eb[e,b] * xb[src[e], b*64 + c]; red into agg[dst[e], c].
// edge_index is INT32 (JAX x64 disabled downcasts int64).
// ---------------------------------------------------------------------------
__global__ void __launch_bounds__(256)
edge_kernel(const int* __restrict__ ei,         // [2, E] int32
            float* __restrict__ agg) {
    int t = blockIdx.x * blockDim.x + threadIdx.x;
    int e = t >> 4;
    int l = t & 15;
    if (e >= N_EDGES) return;

    int src = ei[e];
    int dst = ei[N_EDGES + e];
    if ((unsigned)src >= N_NODES || (unsigned)dst >= N_NODES) return;

    float4 w = g_eb4[e];   // broadcast across the 16 lanes
    const float4* xs = g_xb4 + (size_t)src * (XB_COLS / 4);

    float4 v0 = xs[0 * 16 + l];
    float4 v1 = xs[1 * 16 + l];
    float4 v2 = xs[2 * 16 + l];
    float4 v3 = xs[3 * 16 + l];

    float4 acc;
    acc.x = fmaf(w.x, v0.x, fmaf(w.y, v1.x, fmaf(w.z, v2.x, w.w * v3.x)));
    acc.y = fmaf(w.x, v0.y, fmaf(w.y, v1.y, fmaf(w.z, v2.y, w.w * v3.y)));
    acc.z = fmaf(w.x, v0.z, fmaf(w.y, v1.z, fmaf(w.z, v2.z, w.w * v3.z)));
    acc.w = fmaf(w.x, v0.w, fmaf(w.y, v1.w, fmaf(w.z, v2.w, w.w * v3.w)));

    float* out = agg + (size_t)dst * OUT_CH + l * 4;
    asm volatile("red.global.add.v4.f32 [%0], {%1, %2, %3, %4};"
                 :: "l"(out), "f"(acc.x), "f"(acc.y), "f"(acc.z), "f"(acc.w)
                 : "memory");
}

// ---------------------------------------------------------------------------
// Launch
// ---------------------------------------------------------------------------
extern "C" void kernel_launch(void* const* d_in, const int* in_sizes, int n_in,
                              void* d_out, int out_size) {
    const float* x        = (const float*)d_in[0];
    const int* ei         = (const int*)d_in[1];     // int32
    const float* ea       = (const float*)d_in[2];
    const float* basis    = (const float*)d_in[3];   // [2, 4, 64, 64]
    const float* att      = (const float*)d_in[4];   // [2, 8, 4]
    const float* root     = (const float*)d_in[5];   // [2, 64, 64]
    const float* bias     = (const float*)d_in[6];   // [2, 64]
    float* out            = (float*)d_out;

    void* agg0_p = nullptr;
    cudaGetSymbolAddress(&agg0_p, g_agg04);
    float* agg0 = (float*)agg0_p;

    const int ebBlocks   = (N_EDGES + 255) / 256;
    const int gemmBlocks = (N_NODES + 127) / 128;
    const int edgeBlocks = (N_EDGES * 16 + 255) / 256;

    // ---- Layer 0 ----
    eb_kernel<<<ebBlocks, 256>>>(ea, att);
    node_gemm_kernel<false><<<gemmBlocks, 256>>>(x, basis, root, bias, agg0);
    edge_kernel<<<edgeBlocks, 256>>>(ei, agg0);

    // ---- Layer 1 (input = relu(agg0), output = d_out) ----
    const float* basis1 = basis + N_BASES * IN_CH * OUT_CH;
    const float* att1   = att + N_REL * N_BASES;
    const float* root1  = root + IN_CH * OUT_CH;
    const float* bias1  = bias + OUT_CH;

    eb_kernel<<<ebBlocks, 256>>>(ea, att1);
    node_gemm_kernel<true><<<gemmBlocks, 256>>>(agg0, basis1, root1, bias1, out);
    edge_kernel<<<edgeBlocks, 256>>>(ei, out);
}

// round 5
// speedup vs baseline: 1.6853x; 1.0074x over previous
#include <cuda_runtime.h>

#define N_NODES 50000
#define N_EDGES 800000
#define IN_CH 64
#define OUT_CH 64
#define N_REL 8
#define N_BASES 4
#define XB_COLS 256            // 4 bases * 64 out

// Scratch (__device__ globals; float4-typed => 16B aligned)
__device__ float4 g_xb4[(size_t)N_NODES * XB_COLS / 4];  // node-major [N, 256]
__device__ float4 g_eb4_0[(size_t)N_EDGES];              // layer-0 edge basis weights
__device__ float4 g_eb4_1[(size_t)N_EDGES];              // layer-1 edge basis weights
__device__ float4 g_agg04[(size_t)N_NODES * OUT_CH / 4]; // layer-0 accumulator

// ---------------------------------------------------------------------------
// f32x2 packed helpers (sm_100+ PTX; FFMA2 in SASS — ptxas never auto-fuses)
// ---------------------------------------------------------------------------
__device__ __forceinline__ unsigned long long pack_dup(float b) {
    unsigned long long d;
    asm("mov.b64 %0, {%1, %1};" : "=l"(d) : "f"(b));
    return d;
}
__device__ __forceinline__ void unpack2(float& lo, float& hi, unsigned long long v) {
    asm("mov.b64 {%0, %1}, %2;" : "=f"(lo), "=f"(hi) : "l"(v));
}
__device__ __forceinline__ unsigned long long fma2(unsigned long long a,
                                                   unsigned long long b,
                                                   unsigned long long c) {
    unsigned long long d;
    asm("fma.rn.f32x2 %0, %1, %2, %3;" : "=l"(d) : "l"(a), "l"(b), "l"(c));
    return d;
}

// ---------------------------------------------------------------------------
// Kernel 1: project edge attrs to basis space for BOTH layers in one pass.
// eb_k[e,b] = sum_r ea[e,r] * att_k[r,b]
// ---------------------------------------------------------------------------
__global__ void __launch_bounds__(256)
eb2_kernel(const float* __restrict__ ea,     // [E, 8]
           const float* __restrict__ att0,   // [8, 4]
           const float* __restrict__ att1) { // [8, 4]
    __shared__ float sA0[N_REL][N_BASES];
    __shared__ float sA1[N_REL][N_BASES];
    if (threadIdx.x < N_REL * N_BASES) {
        reinterpret_cast<float*>(sA0)[threadIdx.x] = att0[threadIdx.x];
        reinterpret_cast<float*>(sA1)[threadIdx.x] = att1[threadIdx.x];
    }
    __syncthreads();

    int e = blockIdx.x * blockDim.x + threadIdx.x;
    if (e >= N_EDGES) return;

    const float4* ep = reinterpret_cast<const float4*>(ea + (size_t)e * N_REL);
    float4 a0 = ep[0];
    float4 a1 = ep[1];
    float r[8] = {a0.x, a0.y, a0.z, a0.w, a1.x, a1.y, a1.z, a1.w};

    float4 o0 = make_float4(0.f, 0.f, 0.f, 0.f);
    float4 o1 = make_float4(0.f, 0.f, 0.f, 0.f);
#pragma unroll
    for (int k = 0; k < N_REL; k++) {
        o0.x = fmaf(r[k], sA0[k][0], o0.x);
        o0.y = fmaf(r[k], sA0[k][1], o0.y);
        o0.z = fmaf(r[k], sA0[k][2], o0.z);
        o0.w = fmaf(r[k], sA0[k][3], o0.w);
        o1.x = fmaf(r[k], sA1[k][0], o1.x);
        o1.y = fmaf(r[k], sA1[k][1], o1.y);
        o1.z = fmaf(r[k], sA1[k][2], o1.z);
        o1.w = fmaf(r[k], sA1[k][3], o1.w);
    }
    g_eb4_0[e] = o0;
    g_eb4_1[e] = o1;
}

// ---------------------------------------------------------------------------
// Kernel 2: node GEMM with packed f32x2 FMAs.
//   cols 0..255  -> g_xb4  (xb = h @ basis[b])
//   cols 256..319 -> agg = h @ root + bias
// BM=128, BK=64, 5 col tiles of 64. 256 thr. Per-thread 8 rows x 4 cols,
// accumulated as 4 row-pairs x 4 cols in f32x2 registers.
// A tile stored TRANSPOSED (sAT[ch][row]) so a row-pair is one LDS.64.
// ---------------------------------------------------------------------------
template <bool RELU>
__global__ void __launch_bounds__(256)
node_gemm_kernel(const float* __restrict__ h,
                 const float* __restrict__ basis,  // [4, 64, 64] contiguous tiles
                 const float* __restrict__ root,   // [64, 64]
                 const float* __restrict__ bias,   // [64]
                 float* __restrict__ agg) {
    __shared__ float sAT[64][128];  // 32 KB  [ch][row]
    __shared__ float sB[64][64];    // 16 KB  [ch_in][ch_out]

    const int tid = threadIdx.x;
    const int tx = tid & 15;        // col group (4 cols each)
    const int ty = tid >> 4;        // row group (8 rows each)
    const int nodeBase = blockIdx.x * 128;
    float* xb = reinterpret_cast<float*>(g_xb4);

    // Load A tile transposed: 128 rows x 64 ch
#pragma unroll
    for (int k = tid; k < 128 * 16; k += 256) {
        int row = k >> 4;
        int c4 = k & 15;
        int n = nodeBase + row;
        float4 v = make_float4(0.f, 0.f, 0.f, 0.f);
        if (n < N_NODES)
            v = *reinterpret_cast<const float4*>(h + (size_t)n * IN_CH + c4 * 4);
        if (RELU) {
            v.x = fmaxf(v.x, 0.f); v.y = fmaxf(v.y, 0.f);
            v.z = fmaxf(v.z, 0.f); v.w = fmaxf(v.w, 0.f);
        }
        sAT[c4 * 4 + 0][row] = v.x;
        sAT[c4 * 4 + 1][row] = v.y;
        sAT[c4 * 4 + 2][row] = v.z;
        sAT[c4 * 4 + 3][row] = v.w;
    }
    __syncthreads();

#pragma unroll 1
    for (int jt = 0; jt < 5; jt++) {
        const float* Bsrc = (jt < N_BASES) ? (basis + jt * IN_CH * OUT_CH) : root;
#pragma unroll
        for (int k = tid; k < 64 * 16; k += 256) {
            int i = k >> 4;
            int c4 = k & 15;
            *reinterpret_cast<float4*>(&sB[i][c4 * 4]) =
                *reinterpret_cast<const float4*>(Bsrc + i * OUT_CH + c4 * 4);
        }
        __syncthreads();

        unsigned long long acc2[4][4];   // [row-pair][col]
#pragma unroll
        for (int p = 0; p < 4; p++)
#pragma unroll
            for (int q = 0; q < 4; q++) acc2[p][q] = 0ULL;

#pragma unroll
        for (int i = 0; i < 64; i++) {
            float4 b4 = *reinterpret_cast<const float4*>(&sB[i][tx * 4]);
            unsigned long long bd0 = pack_dup(b4.x);
            unsigned long long bd1 = pack_dup(b4.y);
            unsigned long long bd2 = pack_dup(b4.z);
            unsigned long long bd3 = pack_dup(b4.w);
#pragma unroll
            for (int p = 0; p < 4; p++) {
                unsigned long long a2 =
                    *reinterpret_cast<const unsigned long long*>(&sAT[i][ty * 8 + 2 * p]);
                acc2[p][0] = fma2(a2, bd0, acc2[p][0]);
                acc2[p][1] = fma2(a2, bd1, acc2[p][1]);
                acc2[p][2] = fma2(a2, bd2, acc2[p][2]);
                acc2[p][3] = fma2(a2, bd3, acc2[p][3]);
            }
        }

        // Store: unpack row pairs
        if (jt < N_BASES) {
            int jBase = jt * 64 + tx * 4;
#pragma unroll
            for (int p = 0; p < 4; p++) {
                float4 rA, rB;
                unpack2(rA.x, rB.x, acc2[p][0]);
                unpack2(rA.y, rB.y, acc2[p][1]);
                unpack2(rA.z, rB.z, acc2[p][2]);
                unpack2(rA.w, rB.w, acc2[p][3]);
                int n0 = nodeBase + ty * 8 + 2 * p;
                if (n0 < N_NODES)
                    *reinterpret_cast<float4*>(&xb[(size_t)n0 * XB_COLS + jBase]) = rA;
                if (n0 + 1 < N_NODES)
                    *reinterpret_cast<float4*>(&xb[(size_t)(n0 + 1) * XB_COLS + jBase]) = rB;
            }
        } else {
            int c = tx * 4;
            float4 bv = *reinterpret_cast<const float4*>(bias + c);
#pragma unroll
            for (int p = 0; p < 4; p++) {
                float4 rA, rB;
                unpack2(rA.x, rB.x, acc2[p][0]);
                unpack2(rA.y, rB.y, acc2[p][1]);
                unpack2(rA.z, rB.z, acc2[p][2]);
                unpack2(rA.w, rB.w, acc2[p][3]);
                rA.x += bv.x; rA.y += bv.y; rA.z += bv.z; rA.w += bv.w;
                rB.x += bv.x; rB.y += bv.y; rB.z += bv.z; rB.w += bv.w;
                int n0 = nodeBase + ty * 8 + 2 * p;
                if (n0 < N_NODES)
                    *reinterpret_cast<float4*>(agg + (size_t)n0 * OUT_CH + c) = rA;
                if (n0 + 1 < N_NODES)
                    *reinterpret_cast<float4*>(agg + (size_t)(n0 + 1) * OUT_CH + c) = rB;
            }
        }
        __syncthreads();
    }
}

// ---------------------------------------------------------------------------
// Kernel 3: edge gather + scatter in basis space. Half-warp per edge.
// msg[e,c] = sum_b eb[e,b] * xb[src[e], b*64 + c]; red into agg[dst[e], c].
// edge_index is INT32 (JAX x64 disabled downcasts int64).
// ---------------------------------------------------------------------------
__global__ void __launch_bounds__(256)
edge_kernel(const int* __restrict__ ei,         // [2, E] int32
            const float4* __restrict__ eb,      // [E] basis weights
            float* __restrict__ agg) {
    int t = blockIdx.x * blockDim.x + threadIdx.x;
    int e = t >> 4;
    int l = t & 15;
    if (e >= N_EDGES) return;

    int src = ei[e];
    int dst = ei[N_EDGES + e];
    if ((unsigned)src >= N_NODES || (unsigned)dst >= N_NODES) return;

    float4 w = eb[e];   // broadcast across the 16 lanes
    const float4* xs = g_xb4 + (size_t)src * (XB_COLS / 4);

    float4 v0 = xs[0 * 16 + l];
    float4 v1 = xs[1 * 16 + l];
    float4 v2 = xs[2 * 16 + l];
    float4 v3 = xs[3 * 16 + l];

    float4 acc;
    acc.x = fmaf(w.x, v0.x, fmaf(w.y, v1.x, fmaf(w.z, v2.x, w.w * v3.x)));
    acc.y = fmaf(w.x, v0.y, fmaf(w.y, v1.y, fmaf(w.z, v2.y, w.w * v3.y)));
    acc.z = fmaf(w.x, v0.z, fmaf(w.y, v1.z, fmaf(w.z, v2.z, w.w * v3.z)));
    acc.w = fmaf(w.x, v0.w, fmaf(w.y, v1.w, fmaf(w.z, v2.w, w.w * v3.w)));

    float* out = agg + (size_t)dst * OUT_CH + l * 4;
    asm volatile("red.global.add.v4.f32 [%0], {%1, %2, %3, %4};"
                 :: "l"(out), "f"(acc.x), "f"(acc.y), "f"(acc.z), "f"(acc.w)
                 : "memory");
}

// ---------------------------------------------------------------------------
// Launch
// ---------------------------------------------------------------------------
extern "C" void kernel_launch(void* const* d_in, const int* in_sizes, int n_in,
                              void* d_out, int out_size) {
    const float* x        = (const float*)d_in[0];
    const int* ei         = (const int*)d_in[1];     // int32
    const float* ea       = (const float*)d_in[2];
    const float* basis    = (const float*)d_in[3];   // [2, 4, 64, 64]
    const float* att      = (const float*)d_in[4];   // [2, 8, 4]
    const float* root     = (const float*)d_in[5];   // [2, 64, 64]
    const float* bias     = (const float*)d_in[6];   // [2, 64]
    float* out            = (float*)d_out;

    void* p = nullptr;
    cudaGetSymbolAddress(&p, g_agg04);
    float* agg0 = (float*)p;
    cudaGetSymbolAddress(&p, g_eb4_0);
    float4* eb0 = (float4*)p;
    cudaGetSymbolAddress(&p, g_eb4_1);
    float4* eb1 = (float4*)p;

    const int ebBlocks   = (N_EDGES + 255) / 256;
    const int gemmBlocks = (N_NODES + 127) / 128;
    const int edgeBlocks = (N_EDGES * 16 + 255) / 256;

    const float* basis1 = basis + N_BASES * IN_CH * OUT_CH;
    const float* att1   = att + N_REL * N_BASES;
    const float* root1  = root + IN_CH * OUT_CH;
    const float* bias1  = bias + OUT_CH;

    // Both layers' edge-basis weights in one pass over ea
    eb2_kernel<<<ebBlocks, 256>>>(ea, att, att1);

    // ---- Layer 0 ----
    node_gemm_kernel<false><<<gemmBlocks, 256>>>(x, basis, root, bias, agg0);
    edge_kernel<<<edgeBlocks, 256>>>(ei, eb0, agg0);

    // ---- Layer 1 (input = relu(agg0), output = d_out) ----
    node_gemm_kernel<true><<<gemmBlocks, 256>>>(agg0, basis1, root1, bias1, out);
    edge_kernel<<<edgeBlocks, 256>>>(ei, eb1, out);
}

// round 7
// speedup vs baseline: 2.1269x; 1.2620x over previous
#include <cuda_runtime.h>
#include <cuda_bf16.h>
#include <cstdint>

#define N_NODES 50000
#define N_EDGES 800000
#define IN_CH 64
#define OUT_CH 64
#define N_REL 8
#define N_BASES 4
#define XB_COLS 256            // 4 bases * 64 out
#define GEMM_N 320             // 256 xb cols + 64 root cols

// Scratch (__device__ globals)
__device__ float4 g_xb4[(size_t)N_NODES * XB_COLS / 4];  // node-major [N, 256]
__device__ float4 g_eb4_0[N_EDGES];                      // layer-0 edge basis weights
__device__ float4 g_eb4_1[N_EDGES];                      // layer-1 edge basis weights
__device__ float4 g_agg04[(size_t)N_NODES * OUT_CH / 4]; // layer-0 accumulator
__device__ uint4  g_Bhi4[2 * GEMM_N * 64 * 2 / 16];      // [2][320][64] bf16 hi
__device__ uint4  g_Blo4[2 * GEMM_N * 64 * 2 / 16];      // [2][320][64] bf16 lo

// ---------------------------------------------------------------------------
// Helpers (arch-generic PTX only: ldmatrix + mma.sync, sm_80+)
// ---------------------------------------------------------------------------
__device__ __forceinline__ uint32_t smem_u32(const void* p) {
    uint32_t a;
    asm("{ .reg .u64 t; cvta.to.shared.u64 t, %1; cvt.u32.u64 %0, t; }"
        : "=r"(a) : "l"(p));
    return a;
}
__device__ __forceinline__ void ldsm_x4(uint32_t* r, uint32_t addr) {
    asm volatile("ldmatrix.sync.aligned.m8n8.x4.shared.b16 {%0,%1,%2,%3}, [%4];"
                 : "=r"(r[0]), "=r"(r[1]), "=r"(r[2]), "=r"(r[3]) : "r"(addr));
}
__device__ __forceinline__ void mma16816(float* c, const uint32_t* a, const uint32_t* b) {
    asm volatile(
        "mma.sync.aligned.m16n8k16.row.col.f32.bf16.bf16.f32 "
        "{%0,%1,%2,%3}, {%4,%5,%6,%7}, {%8,%9}, {%0,%1,%2,%3};"
        : "+f"(c[0]), "+f"(c[1]), "+f"(c[2]), "+f"(c[3])
        : "r"(a[0]), "r"(a[1]), "r"(a[2]), "r"(a[3]), "r"(b[0]), "r"(b[1]));
}

// ---------------------------------------------------------------------------
// Kernel 0: split weights into bf16 hi/lo, layout B[l][n=out_col][k=in_ch]
// ---------------------------------------------------------------------------
__global__ void __launch_bounds__(256)
bprep_kernel(const float* __restrict__ basis,   // [2,4,64,64]
             const float* __restrict__ root) {  // [2,64,64]
    int idx = blockIdx.x * blockDim.x + threadIdx.x;
    if (idx >= 2 * GEMM_N * 64) return;
    int l = idx / (GEMM_N * 64);
    int rem = idx - l * (GEMM_N * 64);
    int n = rem >> 6;
    int k = rem & 63;
    float v = (n < 256) ? basis[(((l * 4) + (n >> 6)) * 64 + k) * 64 + (n & 63)]
                        : root[(l * 64 + k) * 64 + (n - 256)];
    __nv_bfloat16 hb = __float2bfloat16(v);
    __nv_bfloat16 lb = __float2bfloat16(v - __bfloat162float(hb));
    reinterpret_cast<unsigned short*>(g_Bhi4)[idx] = __bfloat16_as_ushort(hb);
    reinterpret_cast<unsigned short*>(g_Blo4)[idx] = __bfloat16_as_ushort(lb);
}

// ---------------------------------------------------------------------------
// Kernel 1: project edge attrs to basis space for BOTH layers in one pass
// ---------------------------------------------------------------------------
__global__ void __launch_bounds__(256)
eb2_kernel(const float* __restrict__ ea,     // [E, 8]
           const float* __restrict__ att0,   // [8, 4]
           const float* __restrict__ att1) { // [8, 4]
    __shared__ float sA0[N_REL][N_BASES];
    __shared__ float sA1[N_REL][N_BASES];
    if (threadIdx.x < N_REL * N_BASES) {
        reinterpret_cast<float*>(sA0)[threadIdx.x] = att0[threadIdx.x];
        reinterpret_cast<float*>(sA1)[threadIdx.x] = att1[threadIdx.x];
    }
    __syncthreads();

    int e = blockIdx.x * blockDim.x + threadIdx.x;
    if (e >= N_EDGES) return;

    const float4* ep = reinterpret_cast<const float4*>(ea + (size_t)e * N_REL);
    float4 a0 = ep[0];
    float4 a1 = ep[1];
    float r[8] = {a0.x, a0.y, a0.z, a0.w, a1.x, a1.y, a1.z, a1.w};

    float4 o0 = make_float4(0.f, 0.f, 0.f, 0.f);
    float4 o1 = make_float4(0.f, 0.f, 0.f, 0.f);
#pragma unroll
    for (int k = 0; k < N_REL; k++) {
        o0.x = fmaf(r[k], sA0[k][0], o0.x);
        o0.y = fmaf(r[k], sA0[k][1], o0.y);
        o0.z = fmaf(r[k], sA0[k][2], o0.z);
        o0.w = fmaf(r[k], sA0[k][3], o0.w);
        o1.x = fmaf(r[k], sA1[k][0], o1.x);
        o1.y = fmaf(r[k], sA1[k][1], o1.y);
        o1.z = fmaf(r[k], sA1[k][2], o1.z);
        o1.w = fmaf(r[k], sA1[k][3], o1.w);
    }
    g_eb4_0[e] = o0;
    g_eb4_1[e] = o1;
}

// ---------------------------------------------------------------------------
// Kernel 2: node GEMM on tensor cores via mma.sync, bf16x3 split.
//   D = Ahi*Bhi + Ahi*Blo + Alo*Bhi  (fp32 accum)  ~1e-5 rel precision
// Block = 128 nodes x 320 cols, K=64. 8 warps, warp w -> rows 16w..16w+15.
// 5 col tiles of 64. A frags hoisted to regs; B tile reloaded per nt.
// smem rows padded to 72 bf16 (144B) => conflict-free ldmatrix.
// ---------------------------------------------------------------------------
#define LDA 144                 // bytes per padded row (72 bf16)
#define SM_AHI 0
#define SM_ALO 18432
#define SM_BHI 36864
#define SM_BLO 46080
#define SMEM_BYTES 55296

template <bool RELU>
__global__ void __launch_bounds__(256)
gemm_mma(const float* __restrict__ h,
         const uint4* __restrict__ Bhi,    // [320][64] bf16 (this layer)
         const uint4* __restrict__ Blo,
         const float* __restrict__ bias,
         float* __restrict__ agg) {
    extern __shared__ char smem[];
    const uint32_t sb = smem_u32(smem);
    const int tid = threadIdx.x;
    const int wid = tid >> 5;
    const int lid = tid & 31;
    const int nodeBase = blockIdx.x * 128;
    float* xb = reinterpret_cast<float*>(g_xb4);

    // ---- Convert A rows to bf16 hi/lo into padded smem ----
    if (tid < 128) {
        int n = nodeBase + tid;
        const float4* hp = reinterpret_cast<const float4*>(h + (size_t)n * IN_CH);
        bool valid = (n < N_NODES);
#pragma unroll
        for (int j = 0; j < 8; j++) {   // 8 bf16 per j => one uint4 hi + one lo
            float f[8];
            if (valid) {
                float4 a = hp[2 * j];
                float4 b = hp[2 * j + 1];
                f[0] = a.x; f[1] = a.y; f[2] = a.z; f[3] = a.w;
                f[4] = b.x; f[5] = b.y; f[6] = b.z; f[7] = b.w;
            } else {
#pragma unroll
                for (int t = 0; t < 8; t++) f[t] = 0.f;
            }
            uint32_t hw[4], lw[4];
#pragma unroll
            for (int q = 0; q < 4; q++) {
                float v0 = f[2 * q], v1 = f[2 * q + 1];
                if (RELU) { v0 = fmaxf(v0, 0.f); v1 = fmaxf(v1, 0.f); }
                __nv_bfloat16 h0 = __float2bfloat16(v0);
                __nv_bfloat16 h1 = __float2bfloat16(v1);
                __nv_bfloat16 l0 = __float2bfloat16(v0 - __bfloat162float(h0));
                __nv_bfloat16 l1 = __float2bfloat16(v1 - __bfloat162float(h1));
                hw[q] = (uint32_t)__bfloat16_as_ushort(h0) |
                        ((uint32_t)__bfloat16_as_ushort(h1) << 16);
                lw[q] = (uint32_t)__bfloat16_as_ushort(l0) |
                        ((uint32_t)__bfloat16_as_ushort(l1) << 16);
            }
            *reinterpret_cast<uint4*>(smem + SM_AHI + tid * LDA + j * 16) =
                make_uint4(hw[0], hw[1], hw[2], hw[3]);
            *reinterpret_cast<uint4*>(smem + SM_ALO + tid * LDA + j * 16) =
                make_uint4(lw[0], lw[1], lw[2], lw[3]);
        }
    }
    __syncthreads();

    // ---- Hoist A fragments (4 k-steps x 4 regs, hi + lo) ----
    uint32_t ahi[4][4], alo[4][4];
    {
        uint32_t aoff = (uint32_t)(wid * 16 + (lid & 15)) * LDA + ((lid >> 4) << 4);
#pragma unroll
        for (int ks = 0; ks < 4; ks++) {
            ldsm_x4(ahi[ks], sb + SM_AHI + aoff + ks * 32);
            ldsm_x4(alo[ks], sb + SM_ALO + aoff + ks * 32);
        }
    }

    // B ldmatrix lane offset: mat0/1 = n rows 0-7 (k0-7 / k8-15), mat2/3 = n 8-15
    const uint32_t bLane = (uint32_t)((lid & 7) + ((lid >> 4) << 3)) * LDA +
                           (((lid >> 3) & 1) << 4);

#pragma unroll 1
    for (int nt = 0; nt < 5; nt++) {
        if (nt) __syncthreads();   // protect B smem from previous tile's readers
        // ---- Load B tile (64 rows x 64 bf16, hi+lo) ----
#pragma unroll
        for (int u = tid; u < 512; u += 256) {
            int row = u >> 3;
            int j = u & 7;
            uint32_t off = (uint32_t)row * LDA + j * 16;
            int src = (nt * 64 + row) * 8 + j;
            *reinterpret_cast<uint4*>(smem + SM_BHI + off) = Bhi[src];
            *reinterpret_cast<uint4*>(smem + SM_BLO + off) = Blo[src];
        }
        __syncthreads();

        float acc[8][4];
#pragma unroll
        for (int t = 0; t < 8; t++)
#pragma unroll
            for (int q = 0; q < 4; q++) acc[t][q] = 0.f;

#pragma unroll
        for (int np = 0; np < 4; np++) {       // n16 pair of n8 tiles
            uint32_t bbase = (uint32_t)(np * 16) * LDA + bLane;
#pragma unroll
            for (int ks = 0; ks < 4; ks++) {
                uint32_t bh[4], bl[4];
                ldsm_x4(bh, sb + SM_BHI + bbase + ks * 32);
                ldsm_x4(bl, sb + SM_BLO + bbase + ks * 32);
                mma16816(acc[np * 2 + 0], ahi[ks], bh + 0);
                mma16816(acc[np * 2 + 1], ahi[ks], bh + 2);
                mma16816(acc[np * 2 + 0], ahi[ks], bl + 0);
                mma16816(acc[np * 2 + 1], ahi[ks], bl + 2);
                mma16816(acc[np * 2 + 0], alo[ks], bh + 0);
                mma16816(acc[np * 2 + 1], alo[ks], bh + 2);
            }
        }

        // ---- Epilogue for this col tile ----
        int r0 = nodeBase + wid * 16 + (lid >> 2);
        int cOff = 2 * (lid & 3);
#pragma unroll
        for (int t = 0; t < 8; t++) {
            int col = nt * 64 + t * 8 + cOff;
            if (nt < 4) {
                if (r0 < N_NODES)
                    *reinterpret_cast<float2*>(xb + (size_t)r0 * XB_COLS + col) =
                        make_float2(acc[t][0], acc[t][1]);
                if (r0 + 8 < N_NODES)
                    *reinterpret_cast<float2*>(xb + (size_t)(r0 + 8) * XB_COLS + col) =
                        make_float2(acc[t][2], acc[t][3]);
            } else {
                int oc = col - 256;
                float b0 = __ldg(bias + oc);
                float b1 = __ldg(bias + oc + 1);
                if (r0 < N_NODES)
                    *reinterpret_cast<float2*>(agg + (size_t)r0 * OUT_CH + oc) =
                        make_float2(acc[t][0] + b0, acc[t][1] + b1);
                if (r0 + 8 < N_NODES)
                    *reinterpret_cast<float2*>(agg + (size_t)(r0 + 8) * OUT_CH + oc) =
                        make_float2(acc[t][2] + b0, acc[t][3] + b1);
            }
        }
    }
}

// ---------------------------------------------------------------------------
// Kernel 3: edge gather + scatter in basis space. Half-warp per edge.
// edge_index is INT32 (JAX x64 disabled downcasts int64).
// ---------------------------------------------------------------------------
__global__ void __launch_bounds__(256)
edge_kernel(const int* __restrict__ ei,         // [2, E] int32
            const float4* __restrict__ eb,      // [E] basis weights
            float* __restrict__ agg) {
    int t = blockIdx.x * blockDim.x + threadIdx.x;
    int e = t >> 4;
    int l = t & 15;
    if (e >= N_EDGES) return;

    int src = ei[e];
    int dst = ei[N_EDGES + e];
    if ((unsigned)src >= N_NODES || (unsigned)dst >= N_NODES) return;

    float4 w = eb[e];
    const float4* xs = g_xb4 + (size_t)src * (XB_COLS / 4);

    float4 v0 = xs[0 * 16 + l];
    float4 v1 = xs[1 * 16 + l];
    float4 v2 = xs[2 * 16 + l];
    float4 v3 = xs[3 * 16 + l];

    float4 acc;
    acc.x = fmaf(w.x, v0.x, fmaf(w.y, v1.x, fmaf(w.z, v2.x, w.w * v3.x)));
    acc.y = fmaf(w.x, v0.y, fmaf(w.y, v1.y, fmaf(w.z, v2.y, w.w * v3.y)));
    acc.z = fmaf(w.x, v0.z, fmaf(w.y, v1.z, fmaf(w.z, v2.z, w.w * v3.z)));
    acc.w = fmaf(w.x, v0.w, fmaf(w.y, v1.w, fmaf(w.z, v2.w, w.w * v3.w)));

    float* out = agg + (size_t)dst * OUT_CH + l * 4;
    asm volatile("red.global.add.v4.f32 [%0], {%1, %2, %3, %4};"
                 :: "l"(out), "f"(acc.x), "f"(acc.y), "f"(acc.z), "f"(acc.w)
                 : "memory");
}

// ---------------------------------------------------------------------------
// Launch
// ---------------------------------------------------------------------------
extern "C" void kernel_launch(void* const* d_in, const int* in_sizes, int n_in,
                              void* d_out, int out_size) {
    const float* x        = (const float*)d_in[0];
    const int* ei         = (const int*)d_in[1];     // int32
    const float* ea       = (const float*)d_in[2];
    const float* basis    = (const float*)d_in[3];   // [2, 4, 64, 64]
    const float* att      = (const float*)d_in[4];   // [2, 8, 4]
    const float* root     = (const float*)d_in[5];   // [2, 64, 64]
    const float* bias     = (const float*)d_in[6];   // [2, 64]
    float* out            = (float*)d_out;

    void* p = nullptr;
    cudaGetSymbolAddress(&p, g_agg04);
    float* agg0 = (float*)p;
    cudaGetSymbolAddress(&p, g_eb4_0);
    float4* eb0 = (float4*)p;
    cudaGetSymbolAddress(&p, g_eb4_1);
    float4* eb1 = (float4*)p;
    cudaGetSymbolAddress(&p, g_Bhi4);
    const uint4* Bhi = (const uint4*)p;
    cudaGetSymbolAddress(&p, g_Blo4);
    const uint4* Blo = (const uint4*)p;

    cudaFuncSetAttribute(gemm_mma<false>, cudaFuncAttributeMaxDynamicSharedMemorySize, SMEM_BYTES);
    cudaFuncSetAttribute(gemm_mma<true>,  cudaFuncAttributeMaxDynamicSharedMemorySize, SMEM_BYTES);

    const int ebBlocks    = (N_EDGES + 255) / 256;
    const int gemmBlocks  = (N_NODES + 127) / 128;
    const int edgeBlocks  = (N_EDGES * 16 + 255) / 256;
    const int bprepBlocks = (2 * GEMM_N * 64 + 255) / 256;

    const float* att1  = att + N_REL * N_BASES;
    const float* bias1 = bias + OUT_CH;
    const int layerStride = GEMM_N * 64 * 2 / 16;   // uint4 per layer

    bprep_kernel<<<bprepBlocks, 256>>>(basis, root);
    eb2_kernel<<<ebBlocks, 256>>>(ea, att, att1);

    // ---- Layer 0 ----
    gemm_mma<false><<<gemmBlocks, 256, SMEM_BYTES>>>(x, Bhi, Blo, bias, agg0);
    edge_kernel<<<edgeBlocks, 256>>>(ei, eb0, agg0);

    // ---- Layer 1 ----
    gemm_mma<true><<<gemmBlocks, 256, SMEM_BYTES>>>(agg0, Bhi + layerStride,
                                                    Blo + layerStride, bias1, out);
    edge_kernel<<<edgeBlocks, 256>>>(ei, eb1, out);
}